// round 1
// baseline (speedup 1.0000x reference)
#include <cuda_runtime.h>
#include <cuda_bf16.h>
#include <math.h>

// Problem constants (fixed by the reference)
#define N_FEAT 256
#define HIDDEN 256

// Scratch: two [50000 x 256] fp32 buffers (51.2 MB each). __device__ globals per rules.
#define MAX_NODES 50000
__device__ float g_buf0[MAX_NODES * HIDDEN]; // gemm outputs (h, then g)
__device__ float g_buf1[MAX_NODES * HIDDEN]; // aggregation target (agg1->h1, then agg2)

// ---------------------------------------------------------------------------
// Zero a buffer (float4 grid-stride)
// ---------------------------------------------------------------------------
__global__ void zero_kernel(float* __restrict__ p, int n4) {
    int i = blockIdx.x * blockDim.x + threadIdx.x;
    float4 z = make_float4(0.f, 0.f, 0.f, 0.f);
    for (; i < n4; i += gridDim.x * blockDim.x)
        ((float4*)p)[i] = z;
}

// ---------------------------------------------------------------------------
// SGEMM: C[M,256] = A[M,256] @ B[256,256]
// BM=128 BN=128 BK=16, 256 threads, 8x8 per thread
// ---------------------------------------------------------------------------
#define BM 128
#define BN 128
#define BK 16
#define TM 8
#define TN 8

__global__ __launch_bounds__(256, 2)
void sgemm_kernel(const float* __restrict__ A, const float* __restrict__ B,
                  float* __restrict__ C, int M) {
    const int N = 256, K = 256;
    __shared__ float As[BK][BM];
    __shared__ float Bs[BK][BN];

    int bx = blockIdx.x;          // along N (2 blocks)
    int by = blockIdx.y;          // along M
    int tid = threadIdx.x;        // 0..255
    int tx = tid % 16;            // col group
    int ty = tid / 16;            // row group

    float acc[TM][TN];
#pragma unroll
    for (int i = 0; i < TM; i++)
#pragma unroll
        for (int j = 0; j < TN; j++) acc[i][j] = 0.f;

    for (int k0 = 0; k0 < K; k0 += BK) {
        // Load A tile: 128 rows x 16 cols = 512 float4, 2 per thread (transposed into As)
#pragma unroll
        for (int t = 0; t < 2; t++) {
            int idx = tid + t * 256;
            int row = idx >> 2;            // 0..127
            int c  = (idx & 3) * 4;        // 0,4,8,12
            int grow = by * BM + row;
            float4 v = make_float4(0.f, 0.f, 0.f, 0.f);
            if (grow < M)
                v = *(const float4*)(A + (size_t)grow * K + k0 + c);
            As[c + 0][row] = v.x;
            As[c + 1][row] = v.y;
            As[c + 2][row] = v.z;
            As[c + 3][row] = v.w;
        }
        // Load B tile: 16 rows x 128 cols = 512 float4, 2 per thread
#pragma unroll
        for (int t = 0; t < 2; t++) {
            int idx = tid + t * 256;
            int row = idx >> 5;            // 0..15
            int c  = (idx & 31) * 4;       // 0..124
            float4 v = *(const float4*)(B + (size_t)(k0 + row) * N + bx * BN + c);
            *(float4*)&Bs[row][c] = v;
        }
        __syncthreads();

#pragma unroll
        for (int k = 0; k < BK; k++) {
            float ra[TM], rb[TN];
#pragma unroll
            for (int i = 0; i < TM; i++) ra[i] = As[k][ty * TM + i];
#pragma unroll
            for (int j = 0; j < TN; j++) rb[j] = Bs[k][tx * TN + j];
#pragma unroll
            for (int i = 0; i < TM; i++)
#pragma unroll
                for (int j = 0; j < TN; j++)
                    acc[i][j] += ra[i] * rb[j];
        }
        __syncthreads();
    }

    // Store
#pragma unroll
    for (int i = 0; i < TM; i++) {
        int grow = by * BM + ty * TM + i;
        if (grow < M) {
#pragma unroll
            for (int j = 0; j < TN; j += 4) {
                float4 v = make_float4(acc[i][j], acc[i][j + 1], acc[i][j + 2], acc[i][j + 3]);
                *(float4*)(C + (size_t)grow * N + bx * BN + tx * TN + j) = v;
            }
        }
    }
}

// ---------------------------------------------------------------------------
// Scatter: agg[dst] += w_e * h[src], one warp per edge, red.global.v4.f32
// ---------------------------------------------------------------------------
__global__ __launch_bounds__(256)
void scatter_kernel(const float* __restrict__ h,
                    const int* __restrict__ src,
                    const int* __restrict__ dst,
                    const float* __restrict__ w,
                    float* __restrict__ agg, int E) {
    int gid = blockIdx.x * blockDim.x + threadIdx.x;
    int e = gid >> 5;
    int lane = gid & 31;
    if (e >= E) return;
    int s = src[e];
    int d = dst[e];
    float we = w[e];
    const float4* hs = (const float4*)(h + (size_t)s * HIDDEN);
    float4* ag = (float4*)(agg + (size_t)d * HIDDEN);
#pragma unroll
    for (int t = 0; t < 2; t++) {
        int i = lane + t * 32;   // 0..63 float4s
        float4 v = hs[i];
        v.x *= we; v.y *= we; v.z *= we; v.w *= we;
        asm volatile("red.global.add.v4.f32 [%0], {%1, %2, %3, %4};"
                     :: "l"(ag + i), "f"(v.x), "f"(v.y), "f"(v.z), "f"(v.w)
                     : "memory");
    }
}

// ---------------------------------------------------------------------------
// h1 = relu(agg + b1), in place, float4
// ---------------------------------------------------------------------------
__global__ void relu_bias_kernel(float* __restrict__ p, const float* __restrict__ b, int n4) {
    int i = blockIdx.x * blockDim.x + threadIdx.x;
    for (; i < n4; i += gridDim.x * blockDim.x) {
        float4 v = ((float4*)p)[i];
        int c = (i & 63) * 4;     // column within 256 (256/4 = 64 float4 per row)
        v.x = fmaxf(v.x + b[c + 0], 0.f);
        v.y = fmaxf(v.y + b[c + 1], 0.f);
        v.z = fmaxf(v.z + b[c + 2], 0.f);
        v.w = fmaxf(v.w + b[c + 3], 0.f);
        ((float4*)p)[i] = v;
    }
}

// ---------------------------------------------------------------------------
// Final: per query i, logits = concat(h2[q0], h2[q1]) @ Wl + bl; log_softmax.
// h2[r][f] = agg2[r][f] + b2[f] (bias folded here). One warp per query.
// ---------------------------------------------------------------------------
__global__ __launch_bounds__(256)
void query_kernel(const float* __restrict__ agg2,
                  const float* __restrict__ b2,
                  const int* __restrict__ qe,     // [Q,2]
                  const float* __restrict__ Wl,   // [512,2]
                  const float* __restrict__ bl,   // [2]
                  float* __restrict__ out, int Q) {
    __shared__ float sWl[512][2];
    __shared__ float sb2[256];
    for (int i = threadIdx.x; i < 512; i += blockDim.x) {
        sWl[i][0] = Wl[i * 2 + 0];
        sWl[i][1] = Wl[i * 2 + 1];
    }
    for (int i = threadIdx.x; i < 256; i += blockDim.x) sb2[i] = b2[i];
    __syncthreads();

    int gid = blockIdx.x * blockDim.x + threadIdx.x;
    int q = gid >> 5;
    int lane = gid & 31;
    if (q >= Q) return;

    int r0 = qe[q * 2 + 0];
    int r1 = qe[q * 2 + 1];
    const float* h0 = agg2 + (size_t)r0 * HIDDEN;
    const float* h1 = agg2 + (size_t)r1 * HIDDEN;

    float a0 = 0.f, a1 = 0.f;
#pragma unroll
    for (int t = 0; t < 8; t++) {
        int j = lane + t * 32;
        float v0 = h0[j] + sb2[j];
        float v1 = h1[j] + sb2[j];
        a0 += v0 * sWl[j][0] + v1 * sWl[256 + j][0];
        a1 += v0 * sWl[j][1] + v1 * sWl[256 + j][1];
    }
#pragma unroll
    for (int off = 16; off > 0; off >>= 1) {
        a0 += __shfl_down_sync(0xffffffffu, a0, off);
        a1 += __shfl_down_sync(0xffffffffu, a1, off);
    }
    if (lane == 0) {
        float l0 = a0 + bl[0];
        float l1 = a1 + bl[1];
        float m = fmaxf(l0, l1);
        float lse = m + logf(expf(l0 - m) + expf(l1 - m));
        out[q * 2 + 0] = l0 - lse;
        out[q * 2 + 1] = l1 - lse;
    }
}

// ---------------------------------------------------------------------------
// Launch
// ---------------------------------------------------------------------------
extern "C" void kernel_launch(void* const* d_in, const int* in_sizes, int n_in,
                              void* d_out, int out_size) {
    const float* x   = (const float*)d_in[0];
    const int*   ei  = (const int*)d_in[1];       // [2, E]
    const int*   qe  = (const int*)d_in[2];       // [Q, 2]
    const float* ew  = (const float*)d_in[3];     // [E]
    const float* W1  = (const float*)d_in[4];
    const float* b1  = (const float*)d_in[5];
    const float* W2  = (const float*)d_in[6];
    const float* b2  = (const float*)d_in[7];
    const float* Wl  = (const float*)d_in[8];
    const float* bl  = (const float*)d_in[9];
    float* out = (float*)d_out;

    int Nn = in_sizes[0] / N_FEAT;    // 50000
    int E  = in_sizes[1] / 2;         // 1e6
    int Q  = in_sizes[2] / 2;         // 1e5
    const int* src = ei;
    const int* dst = ei + E;

    float* buf0; cudaGetSymbolAddress((void**)&buf0, g_buf0);
    float* buf1; cudaGetSymbolAddress((void**)&buf1, g_buf1);

    int n4 = Nn * HIDDEN / 4;
    dim3 gemm_grid(256 / BN, (Nn + BM - 1) / BM);
    int scatter_blocks = (int)(((long long)E * 32 + 255) / 256);

    // h = X @ W1  -> buf0
    sgemm_kernel<<<gemm_grid, 256>>>(x, W1, buf0, Nn);
    // agg1 = 0
    zero_kernel<<<12500, 256>>>(buf1, n4);
    // agg1[dst] += w * h[src]
    scatter_kernel<<<scatter_blocks, 256>>>(buf0, src, dst, ew, buf1, E);
    // h1 = relu(agg1 + b1) in place
    relu_bias_kernel<<<12500, 256>>>(buf1, b1, n4);
    // g = h1 @ W2 -> buf0
    sgemm_kernel<<<gemm_grid, 256>>>(buf1, W2, buf0, Nn);
    // agg2 = 0 (reuse buf1)
    zero_kernel<<<12500, 256>>>(buf1, n4);
    // agg2[dst] += w * g[src]
    scatter_kernel<<<scatter_blocks, 256>>>(buf0, src, dst, ew, buf1, E);
    // logits + log_softmax (b2, Wl, bl folded)
    query_kernel<<<(Q * 32 + 255) / 256, 256>>>(buf1, b2, qe, Wl, bl, out, Q);
}

// round 3
// speedup vs baseline: 1.0912x; 1.0912x over previous
#include <cuda_runtime.h>
#include <cuda_bf16.h>
#include <math.h>

#define N_FEAT 256
#define HIDDEN 256
#define MAX_NODES 50000
#define MAX_EDGES 1000000

// Scratch (__device__ globals per allocation rules)
__device__ float g_buf0[MAX_NODES * HIDDEN]; // gemm outputs (h, then g)
__device__ float g_buf1[MAX_NODES * HIDDEN]; // aggregation outputs (h1, then agg2)
__device__ int   g_cnt[MAX_NODES];
__device__ int   g_rowptr[MAX_NODES + 1];
__device__ int   g_cursor[MAX_NODES];
__device__ int   g_ssrc[MAX_EDGES];
__device__ float g_sw[MAX_EDGES];

// ---------------------------------------------------------------------------
// CSR build: zero counts -> histogram -> scan -> fill (edges sorted by dst)
// ---------------------------------------------------------------------------
__global__ void zero_int_kernel(int* __restrict__ p, int n) {
    int i = blockIdx.x * blockDim.x + threadIdx.x;
    for (; i < n; i += gridDim.x * blockDim.x) p[i] = 0;
}

__global__ void hist_kernel(const int* __restrict__ dst, int* __restrict__ cnt, int E) {
    int i = blockIdx.x * blockDim.x + threadIdx.x;
    for (; i < E; i += gridDim.x * blockDim.x)
        atomicAdd(&cnt[dst[i]], 1);
}

// single-block exclusive scan (1024 threads, warp-shuffle based)
__global__ void scan_kernel(const int* __restrict__ cnt, int* __restrict__ rowptr,
                            int* __restrict__ cursor, int n) {
    __shared__ int warpsums[32];
    __shared__ int carry_s;
    int lane = threadIdx.x & 31, wid = threadIdx.x >> 5;
    if (threadIdx.x == 0) carry_s = 0;
    __syncthreads();
    for (int base = 0; base < n; base += blockDim.x) {
        int i = base + threadIdx.x;
        int v = (i < n) ? cnt[i] : 0;
        int x = v;
#pragma unroll
        for (int off = 1; off < 32; off <<= 1) {
            int t = __shfl_up_sync(0xffffffffu, x, off);
            if (lane >= off) x += t;
        }
        if (lane == 31) warpsums[wid] = x;
        __syncthreads();
        if (wid == 0) {
            int s = warpsums[lane];
#pragma unroll
            for (int off = 1; off < 32; off <<= 1) {
                int t = __shfl_up_sync(0xffffffffu, s, off);
                if (lane >= off) s += t;
            }
            warpsums[lane] = s; // inclusive warp-sum scan
        }
        __syncthreads();
        int warp_off = (wid == 0) ? 0 : warpsums[wid - 1];
        int excl = carry_s + warp_off + x - v;
        if (i < n) { rowptr[i] = excl; cursor[i] = excl; }
        __syncthreads();
        if (threadIdx.x == 0) carry_s += warpsums[31];
        __syncthreads();
    }
    if (threadIdx.x == 0) rowptr[n] = carry_s;
}

__global__ void fill_kernel(const int* __restrict__ src, const int* __restrict__ dst,
                            const float* __restrict__ w, int* __restrict__ cursor,
                            int* __restrict__ ssrc, float* __restrict__ sw, int E) {
    int i = blockIdx.x * blockDim.x + threadIdx.x;
    for (; i < E; i += gridDim.x * blockDim.x) {
        int p = atomicAdd(&cursor[dst[i]], 1);
        ssrc[p] = src[i];
        sw[p] = w[i];
    }
}

// ---------------------------------------------------------------------------
// SGEMM: C[M,256] = A[M,256] @ B[256,256]; BM=BN=128, BK=16, 256 thr, 8x8/thr
// ---------------------------------------------------------------------------
#define BM 128
#define BN 128
#define BK 16
#define TM 8
#define TN 8

__global__ __launch_bounds__(256, 2)
void sgemm_kernel(const float* __restrict__ A, const float* __restrict__ B,
                  float* __restrict__ C, int M) {
    const int N = 256, K = 256;
    __shared__ float As[BK][BM];
    __shared__ float Bs[BK][BN];

    int bx = blockIdx.x, by = blockIdx.y;
    int tid = threadIdx.x;
    int tx = tid % 16, ty = tid / 16;

    float acc[TM][TN];
#pragma unroll
    for (int i = 0; i < TM; i++)
#pragma unroll
        for (int j = 0; j < TN; j++) acc[i][j] = 0.f;

    for (int k0 = 0; k0 < K; k0 += BK) {
#pragma unroll
        for (int t = 0; t < 2; t++) {
            int idx = tid + t * 256;
            int row = idx >> 2;
            int c = (idx & 3) * 4;
            int grow = by * BM + row;
            float4 v = make_float4(0.f, 0.f, 0.f, 0.f);
            if (grow < M)
                v = *(const float4*)(A + (size_t)grow * K + k0 + c);
            As[c + 0][row] = v.x;
            As[c + 1][row] = v.y;
            As[c + 2][row] = v.z;
            As[c + 3][row] = v.w;
        }
#pragma unroll
        for (int t = 0; t < 2; t++) {
            int idx = tid + t * 256;
            int row = idx >> 5;
            int c = (idx & 31) * 4;
            float4 v = *(const float4*)(B + (size_t)(k0 + row) * N + bx * BN + c);
            *(float4*)&Bs[row][c] = v;
        }
        __syncthreads();

#pragma unroll
        for (int k = 0; k < BK; k++) {
            float ra[TM], rb[TN];
#pragma unroll
            for (int i = 0; i < TM; i++) ra[i] = As[k][ty * TM + i];
#pragma unroll
            for (int j = 0; j < TN; j++) rb[j] = Bs[k][tx * TN + j];
#pragma unroll
            for (int i = 0; i < TM; i++)
#pragma unroll
                for (int j = 0; j < TN; j++)
                    acc[i][j] += ra[i] * rb[j];
        }
        __syncthreads();
    }

#pragma unroll
    for (int i = 0; i < TM; i++) {
        int grow = by * BM + ty * TM + i;
        if (grow < M) {
#pragma unroll
            for (int j = 0; j < TN; j += 4) {
                float4 v = make_float4(acc[i][j], acc[i][j + 1], acc[i][j + 2], acc[i][j + 3]);
                *(float4*)(C + (size_t)grow * N + bx * BN + tx * TN + j) = v;
            }
        }
    }
}

// ---------------------------------------------------------------------------
// Gather aggregation: out[node][f] = epilogue( sum_{e in CSR row} w_e * h[src_e][f] )
// One 256-thread block per dst node; each thread owns one feature column.
// RELU=1: out = relu(acc + bias[f]); RELU=0: out = acc (bias folded later)
// ---------------------------------------------------------------------------
template <int RELU>
__global__ __launch_bounds__(256)
void gather_kernel(const float* __restrict__ h,
                   const int* __restrict__ rowptr,
                   const int* __restrict__ ssrc,
                   const float* __restrict__ sw,
                   const float* __restrict__ bias,
                   float* __restrict__ out) {
    int node = blockIdx.x;
    int f = threadIdx.x;
    int beg = rowptr[node], end = rowptr[node + 1];

    float acc = 0.f;
    int i = beg;
    for (; i + 3 < end; i += 4) {
        int s0 = __ldg(&ssrc[i + 0]), s1 = __ldg(&ssrc[i + 1]);
        int s2 = __ldg(&ssrc[i + 2]), s3 = __ldg(&ssrc[i + 3]);
        float w0 = __ldg(&sw[i + 0]), w1 = __ldg(&sw[i + 1]);
        float w2 = __ldg(&sw[i + 2]), w3 = __ldg(&sw[i + 3]);
        float v0 = h[(size_t)s0 * HIDDEN + f];
        float v1 = h[(size_t)s1 * HIDDEN + f];
        float v2 = h[(size_t)s2 * HIDDEN + f];
        float v3 = h[(size_t)s3 * HIDDEN + f];
        acc += w0 * v0;
        acc += w1 * v1;
        acc += w2 * v2;
        acc += w3 * v3;
    }
    for (; i < end; i++) {
        int s = __ldg(&ssrc[i]);
        acc += __ldg(&sw[i]) * h[(size_t)s * HIDDEN + f];
    }

    if (RELU)
        out[(size_t)node * HIDDEN + f] = fmaxf(acc + bias[f], 0.f);
    else
        out[(size_t)node * HIDDEN + f] = acc;
}

// ---------------------------------------------------------------------------
// Query: logits = concat(h2[q0], h2[q1]) @ Wl + bl; log_softmax.
// h2[r][f] = agg2[r][f] + b2[f] folded here. One warp per query.
// ---------------------------------------------------------------------------
__global__ __launch_bounds__(256)
void query_kernel(const float* __restrict__ agg2,
                  const float* __restrict__ b2,
                  const int* __restrict__ qe,
                  const float* __restrict__ Wl,
                  const float* __restrict__ bl,
                  float* __restrict__ out, int Q) {
    __shared__ float sWl[512][2];
    __shared__ float sb2[256];
    for (int i = threadIdx.x; i < 512; i += blockDim.x) {
        sWl[i][0] = Wl[i * 2 + 0];
        sWl[i][1] = Wl[i * 2 + 1];
    }
    for (int i = threadIdx.x; i < 256; i += blockDim.x) sb2[i] = b2[i];
    __syncthreads();

    int gid = blockIdx.x * blockDim.x + threadIdx.x;
    int q = gid >> 5;
    int lane = gid & 31;
    if (q >= Q) return;

    int r0 = qe[q * 2 + 0];
    int r1 = qe[q * 2 + 1];
    const float* h0 = agg2 + (size_t)r0 * HIDDEN;
    const float* h1 = agg2 + (size_t)r1 * HIDDEN;

    float a0 = 0.f, a1 = 0.f;
#pragma unroll
    for (int t = 0; t < 8; t++) {
        int j = lane + t * 32;
        float v0 = h0[j] + sb2[j];
        float v1 = h1[j] + sb2[j];
        a0 += v0 * sWl[j][0] + v1 * sWl[256 + j][0];
        a1 += v0 * sWl[j][1] + v1 * sWl[256 + j][1];
    }
#pragma unroll
    for (int off = 16; off > 0; off >>= 1) {
        a0 += __shfl_down_sync(0xffffffffu, a0, off);
        a1 += __shfl_down_sync(0xffffffffu, a1, off);
    }
    if (lane == 0) {
        float l0 = a0 + bl[0];
        float l1 = a1 + bl[1];
        float m = fmaxf(l0, l1);
        float lse = m + logf(expf(l0 - m) + expf(l1 - m));
        out[q * 2 + 0] = l0 - lse;
        out[q * 2 + 1] = l1 - lse;
    }
}

// ---------------------------------------------------------------------------
// Launch
// ---------------------------------------------------------------------------
extern "C" void kernel_launch(void* const* d_in, const int* in_sizes, int n_in,
                              void* d_out, int out_size) {
    const float* x  = (const float*)d_in[0];
    const int*   ei = (const int*)d_in[1];
    const int*   qe = (const int*)d_in[2];
    const float* ew = (const float*)d_in[3];
    const float* W1 = (const float*)d_in[4];
    const float* b1 = (const float*)d_in[5];
    const float* W2 = (const float*)d_in[6];
    const float* b2 = (const float*)d_in[7];
    const float* Wl = (const float*)d_in[8];
    const float* bl = (const float*)d_in[9];
    float* out = (float*)d_out;

    int Nn = in_sizes[0] / N_FEAT;
    int E  = in_sizes[1] / 2;
    int Q  = in_sizes[2] / 2;
    const int* src = ei;
    const int* dst = ei + E;

    float* buf0;  cudaGetSymbolAddress((void**)&buf0, g_buf0);
    float* buf1;  cudaGetSymbolAddress((void**)&buf1, g_buf1);
    int* cnt;     cudaGetSymbolAddress((void**)&cnt, g_cnt);
    int* rowptr;  cudaGetSymbolAddress((void**)&rowptr, g_rowptr);
    int* cursor;  cudaGetSymbolAddress((void**)&cursor, g_cursor);
    int* ssrc;    cudaGetSymbolAddress((void**)&ssrc, g_ssrc);
    float* sw;    cudaGetSymbolAddress((void**)&sw, g_sw);

    dim3 gemm_grid(256 / BN, (Nn + BM - 1) / BM);

    // CSR build (shared by both aggregation layers)
    zero_int_kernel<<<196, 256>>>(cnt, Nn);
    hist_kernel<<<1024, 256>>>(dst, cnt, E);
    scan_kernel<<<1, 1024>>>(cnt, rowptr, cursor, Nn);
    fill_kernel<<<1024, 256>>>(src, dst, ew, cursor, ssrc, sw, E);

    // h = X @ W1 -> buf0
    sgemm_kernel<<<gemm_grid, 256>>>(x, W1, buf0, Nn);
    // h1 = relu(gather(h) + b1) -> buf1
    gather_kernel<1><<<Nn, 256>>>(buf0, rowptr, ssrc, sw, b1, buf1);
    // g = h1 @ W2 -> buf0
    sgemm_kernel<<<gemm_grid, 256>>>(buf1, W2, buf0, Nn);
    // agg2 = gather(g) -> buf1 (b2 folded into query)
    gather_kernel<0><<<Nn, 256>>>(buf0, rowptr, ssrc, sw, b2, buf1);
    // logits + log_softmax
    query_kernel<<<(Q * 32 + 255) / 256, 256>>>(buf1, b2, qe, Wl, bl, out, Q);
}

// round 6
// speedup vs baseline: 1.5440x; 1.4149x over previous
#include <cuda_runtime.h>
#include <cuda_bf16.h>
#include <cstdint>
#include <math.h>

#define N_FEAT 256
#define HIDDEN 256
#define MAX_NODES 50000
#define MAX_EDGES 1000000

// Scratch (__device__ globals per allocation rules)
__device__ float g_buf0[MAX_NODES * HIDDEN]; // gemm outputs (h, then g)
__device__ float g_buf1[MAX_NODES * HIDDEN]; // aggregation outputs (h1, then agg2)
__device__ int   g_cnt[MAX_NODES];
__device__ int   g_rowptr[MAX_NODES + 1];
__device__ int   g_cursor[MAX_NODES];
__device__ int   g_ssrc[MAX_EDGES];
__device__ float g_sw[MAX_EDGES];

// ---------------------------------------------------------------------------
// CSR build: zero counts -> histogram -> scan -> fill (edges sorted by dst)
// ---------------------------------------------------------------------------
__global__ void zero_int_kernel(int* __restrict__ p, int n) {
    int i = blockIdx.x * blockDim.x + threadIdx.x;
    for (; i < n; i += gridDim.x * blockDim.x) p[i] = 0;
}

__global__ void hist_kernel(const int* __restrict__ dst, int* __restrict__ cnt, int E) {
    int i = blockIdx.x * blockDim.x + threadIdx.x;
    for (; i < E; i += gridDim.x * blockDim.x)
        atomicAdd(&cnt[dst[i]], 1);
}

// single-block exclusive scan (1024 threads, warp-shuffle based)
__global__ void scan_kernel(const int* __restrict__ cnt, int* __restrict__ rowptr,
                            int* __restrict__ cursor, int n) {
    __shared__ int warpsums[32];
    __shared__ int carry_s;
    int lane = threadIdx.x & 31, wid = threadIdx.x >> 5;
    if (threadIdx.x == 0) carry_s = 0;
    __syncthreads();
    for (int base = 0; base < n; base += blockDim.x) {
        int i = base + threadIdx.x;
        int v = (i < n) ? cnt[i] : 0;
        int x = v;
#pragma unroll
        for (int off = 1; off < 32; off <<= 1) {
            int t = __shfl_up_sync(0xffffffffu, x, off);
            if (lane >= off) x += t;
        }
        if (lane == 31) warpsums[wid] = x;
        __syncthreads();
        if (wid == 0) {
            int s = warpsums[lane];
#pragma unroll
            for (int off = 1; off < 32; off <<= 1) {
                int t = __shfl_up_sync(0xffffffffu, s, off);
                if (lane >= off) s += t;
            }
            warpsums[lane] = s; // inclusive warp-sum scan
        }
        __syncthreads();
        int warp_off = (wid == 0) ? 0 : warpsums[wid - 1];
        int excl = carry_s + warp_off + x - v;
        if (i < n) { rowptr[i] = excl; cursor[i] = excl; }
        __syncthreads();
        if (threadIdx.x == 0) carry_s += warpsums[31];
        __syncthreads();
    }
    if (threadIdx.x == 0) rowptr[n] = carry_s;
}

__global__ void fill_kernel(const int* __restrict__ src, const int* __restrict__ dst,
                            const float* __restrict__ w, int* __restrict__ cursor,
                            int* __restrict__ ssrc, float* __restrict__ sw, int E) {
    int i = blockIdx.x * blockDim.x + threadIdx.x;
    for (; i < E; i += gridDim.x * blockDim.x) {
        int p = atomicAdd(&cursor[dst[i]], 1);
        ssrc[p] = src[i];
        sw[p] = w[i];
    }
}

// ---------------------------------------------------------------------------
// TF32 tensor-core GEMM: C[M,256] = A[M,256] @ B[256,256]
// Block tile 128x128x32, 256 threads (8 warps), warp tile 32x64,
// mma.sync.aligned.m16n8k8.row.col.f32.tf32.tf32.f32, fp32 accumulate.
// A/B staged through smem with cvt.rna.tf32 rounding.
// ---------------------------------------------------------------------------
#define GBM 128
#define GBN 128
#define GBK 32
#define GPAD 4

__device__ __forceinline__ float tf32_rna(float x) {
    unsigned int u;
    asm("cvt.rna.tf32.f32 %0, %1;" : "=r"(u) : "f"(x));
    return __uint_as_float(u);
}

__device__ __forceinline__ void mma_tf32(float c[4], const unsigned int a[4], const unsigned int b[2]) {
    asm volatile(
        "mma.sync.aligned.m16n8k8.row.col.f32.tf32.tf32.f32 "
        "{%0,%1,%2,%3}, {%4,%5,%6,%7}, {%8,%9}, {%0,%1,%2,%3};"
        : "+f"(c[0]), "+f"(c[1]), "+f"(c[2]), "+f"(c[3])
        : "r"(a[0]), "r"(a[1]), "r"(a[2]), "r"(a[3]), "r"(b[0]), "r"(b[1]));
}

__global__ __launch_bounds__(256, 2)
void gemm_tf32_kernel(const float* __restrict__ A, const float* __restrict__ B,
                      float* __restrict__ C, int M) {
    const int N = 256, K = 256;
    __shared__ float As[GBK][GBM + GPAD]; // [k][m]
    __shared__ float Bs[GBK][GBN + GPAD]; // [k][n]

    int tid = threadIdx.x;
    int wid = tid >> 5, lane = tid & 31;
    int warp_m = wid & 3;   // 4 warps along M, 32 rows each
    int warp_n = wid >> 2;  // 2 warps along N, 64 cols each
    int gID = lane >> 2;    // 0..7
    int tig = lane & 3;     // 0..3
    int bx = blockIdx.x, by = blockIdx.y;

    float c[2][8][4];
#pragma unroll
    for (int mi = 0; mi < 2; mi++)
#pragma unroll
        for (int ni = 0; ni < 8; ni++)
#pragma unroll
            for (int r = 0; r < 4; r++) c[mi][ni][r] = 0.f;

    for (int k0 = 0; k0 < K; k0 += GBK) {
        // A tile: 128 rows x 32 cols -> As[k][m] (transposed), tf32-rounded
#pragma unroll
        for (int t = 0; t < 4; t++) {
            int idx = tid + t * 256;          // 0..1023 float4 slots
            int row = idx >> 3;               // 0..127
            int c4 = (idx & 7) * 4;           // 0..28
            int grow = by * GBM + row;
            float4 v = make_float4(0.f, 0.f, 0.f, 0.f);
            if (grow < M)
                v = *(const float4*)(A + (size_t)grow * K + k0 + c4);
            As[c4 + 0][row] = tf32_rna(v.x);
            As[c4 + 1][row] = tf32_rna(v.y);
            As[c4 + 2][row] = tf32_rna(v.z);
            As[c4 + 3][row] = tf32_rna(v.w);
        }
        // B tile: 32 rows (k) x 128 cols -> Bs[k][n], tf32-rounded
#pragma unroll
        for (int t = 0; t < 4; t++) {
            int idx = tid + t * 256;
            int r = idx >> 5;                 // 0..31
            int c4 = (idx & 31) * 4;          // 0..124
            float4 v = *(const float4*)(B + (size_t)(k0 + r) * N + bx * GBN + c4);
            v.x = tf32_rna(v.x); v.y = tf32_rna(v.y);
            v.z = tf32_rna(v.z); v.w = tf32_rna(v.w);
            *(float4*)&Bs[r][c4] = v;
        }
        __syncthreads();

#pragma unroll
        for (int ks = 0; ks < 4; ks++) {
            int kb = ks * 8;
            unsigned int a[2][4];
#pragma unroll
            for (int mi = 0; mi < 2; mi++) {
                int ar = warp_m * 32 + mi * 16 + gID;
                a[mi][0] = __float_as_uint(As[kb + tig][ar]);
                a[mi][1] = __float_as_uint(As[kb + tig][ar + 8]);
                a[mi][2] = __float_as_uint(As[kb + tig + 4][ar]);
                a[mi][3] = __float_as_uint(As[kb + tig + 4][ar + 8]);
            }
            unsigned int b[8][2];
#pragma unroll
            for (int ni = 0; ni < 8; ni++) {
                int bc = warp_n * 64 + ni * 8 + gID;
                b[ni][0] = __float_as_uint(Bs[kb + tig][bc]);
                b[ni][1] = __float_as_uint(Bs[kb + tig + 4][bc]);
            }
#pragma unroll
            for (int mi = 0; mi < 2; mi++)
#pragma unroll
                for (int ni = 0; ni < 8; ni++)
                    mma_tf32(c[mi][ni], a[mi], b[ni]);
        }
        __syncthreads();
    }

    // Store: c0,c1 -> (row, 2tig..+1); c2,c3 -> (row+8, ...)
#pragma unroll
    for (int mi = 0; mi < 2; mi++) {
        int row0 = by * GBM + warp_m * 32 + mi * 16 + gID;
#pragma unroll
        for (int ni = 0; ni < 8; ni++) {
            int col = bx * GBN + warp_n * 64 + ni * 8 + tig * 2;
            if (row0 < M)
                *(float2*)(C + (size_t)row0 * N + col) = make_float2(c[mi][ni][0], c[mi][ni][1]);
            if (row0 + 8 < M)
                *(float2*)(C + (size_t)(row0 + 8) * N + col) = make_float2(c[mi][ni][2], c[mi][ni][3]);
        }
    }
}

// ---------------------------------------------------------------------------
// Gather aggregation: out[node][f] = epilogue( sum_{e in CSR row} w_e * h[src_e][f] )
// One 256-thread block per dst node; each thread owns one feature column.
// ---------------------------------------------------------------------------
template <int RELU>
__global__ __launch_bounds__(256)
void gather_kernel(const float* __restrict__ h,
                   const int* __restrict__ rowptr,
                   const int* __restrict__ ssrc,
                   const float* __restrict__ sw,
                   const float* __restrict__ bias,
                   float* __restrict__ out) {
    int node = blockIdx.x;
    int f = threadIdx.x;
    int beg = rowptr[node], end = rowptr[node + 1];

    float acc = 0.f;
    int i = beg;
    for (; i + 3 < end; i += 4) {
        int s0 = __ldg(&ssrc[i + 0]), s1 = __ldg(&ssrc[i + 1]);
        int s2 = __ldg(&ssrc[i + 2]), s3 = __ldg(&ssrc[i + 3]);
        float w0 = __ldg(&sw[i + 0]), w1 = __ldg(&sw[i + 1]);
        float w2 = __ldg(&sw[i + 2]), w3 = __ldg(&sw[i + 3]);
        float v0 = h[(size_t)s0 * HIDDEN + f];
        float v1 = h[(size_t)s1 * HIDDEN + f];
        float v2 = h[(size_t)s2 * HIDDEN + f];
        float v3 = h[(size_t)s3 * HIDDEN + f];
        acc += w0 * v0;
        acc += w1 * v1;
        acc += w2 * v2;
        acc += w3 * v3;
    }
    for (; i < end; i++) {
        int s = __ldg(&ssrc[i]);
        acc += __ldg(&sw[i]) * h[(size_t)s * HIDDEN + f];
    }

    if (RELU)
        out[(size_t)node * HIDDEN + f] = fmaxf(acc + bias[f], 0.f);
    else
        out[(size_t)node * HIDDEN + f] = acc;
}

// ---------------------------------------------------------------------------
// Query: logits = concat(h2[q0], h2[q1]) @ Wl + bl; log_softmax. One warp/query.
// ---------------------------------------------------------------------------
__global__ __launch_bounds__(256)
void query_kernel(const float* __restrict__ agg2,
                  const float* __restrict__ b2,
                  const int* __restrict__ qe,
                  const float* __restrict__ Wl,
                  const float* __restrict__ bl,
                  float* __restrict__ out, int Q) {
    __shared__ float sWl[512][2];
    __shared__ float sb2[256];
    for (int i = threadIdx.x; i < 512; i += blockDim.x) {
        sWl[i][0] = Wl[i * 2 + 0];
        sWl[i][1] = Wl[i * 2 + 1];
    }
    for (int i = threadIdx.x; i < 256; i += blockDim.x) sb2[i] = b2[i];
    __syncthreads();

    int gid = blockIdx.x * blockDim.x + threadIdx.x;
    int q = gid >> 5;
    int lane = gid & 31;
    if (q >= Q) return;

    int r0 = qe[q * 2 + 0];
    int r1 = qe[q * 2 + 1];
    const float* h0 = agg2 + (size_t)r0 * HIDDEN;
    const float* h1 = agg2 + (size_t)r1 * HIDDEN;

    float a0 = 0.f, a1 = 0.f;
#pragma unroll
    for (int t = 0; t < 8; t++) {
        int j = lane + t * 32;
        float v0 = h0[j] + sb2[j];
        float v1 = h1[j] + sb2[j];
        a0 += v0 * sWl[j][0] + v1 * sWl[256 + j][0];
        a1 += v0 * sWl[j][1] + v1 * sWl[256 + j][1];
    }
#pragma unroll
    for (int off = 16; off > 0; off >>= 1) {
        a0 += __shfl_down_sync(0xffffffffu, a0, off);
        a1 += __shfl_down_sync(0xffffffffu, a1, off);
    }
    if (lane == 0) {
        float l0 = a0 + bl[0];
        float l1 = a1 + bl[1];
        float m = fmaxf(l0, l1);
        float lse = m + logf(expf(l0 - m) + expf(l1 - m));
        out[q * 2 + 0] = l0 - lse;
        out[q * 2 + 1] = l1 - lse;
    }
}

// ---------------------------------------------------------------------------
// Launch
// ---------------------------------------------------------------------------
extern "C" void kernel_launch(void* const* d_in, const int* in_sizes, int n_in,
                              void* d_out, int out_size) {
    const float* x  = (const float*)d_in[0];
    const int*   ei = (const int*)d_in[1];
    const int*   qe = (const int*)d_in[2];
    const float* ew = (const float*)d_in[3];
    const float* W1 = (const float*)d_in[4];
    const float* b1 = (const float*)d_in[5];
    const float* W2 = (const float*)d_in[6];
    const float* b2 = (const float*)d_in[7];
    const float* Wl = (const float*)d_in[8];
    const float* bl = (const float*)d_in[9];
    float* out = (float*)d_out;

    int Nn = in_sizes[0] / N_FEAT;
    int E  = in_sizes[1] / 2;
    int Q  = in_sizes[2] / 2;
    const int* src = ei;
    const int* dst = ei + E;

    float* buf0;  cudaGetSymbolAddress((void**)&buf0, g_buf0);
    float* buf1;  cudaGetSymbolAddress((void**)&buf1, g_buf1);
    int* cnt;     cudaGetSymbolAddress((void**)&cnt, g_cnt);
    int* rowptr;  cudaGetSymbolAddress((void**)&rowptr, g_rowptr);
    int* cursor;  cudaGetSymbolAddress((void**)&cursor, g_cursor);
    int* ssrc;    cudaGetSymbolAddress((void**)&ssrc, g_ssrc);
    float* sw;    cudaGetSymbolAddress((void**)&sw, g_sw);

    dim3 gemm_grid(256 / GBN, (Nn + GBM - 1) / GBM);

    // CSR build (shared by both aggregation layers)
    zero_int_kernel<<<196, 256>>>(cnt, Nn);
    hist_kernel<<<1024, 256>>>(dst, cnt, E);
    scan_kernel<<<1, 1024>>>(cnt, rowptr, cursor, Nn);
    fill_kernel<<<1024, 256>>>(src, dst, ew, cursor, ssrc, sw, E);

    // h = X @ W1 -> buf0 (tf32 tensor cores)
    gemm_tf32_kernel<<<gemm_grid, 256>>>(x, W1, buf0, Nn);
    // h1 = relu(gather(h) + b1) -> buf1
    gather_kernel<1><<<Nn, 256>>>(buf0, rowptr, ssrc, sw, b1, buf1);
    // g = h1 @ W2 -> buf0 (tf32 tensor cores)
    gemm_tf32_kernel<<<gemm_grid, 256>>>(buf1, W2, buf0, Nn);
    // agg2 = gather(g) -> buf1 (b2 folded into query)
    gather_kernel<0><<<Nn, 256>>>(buf0, rowptr, ssrc, sw, b2, buf1);
    // logits + log_softmax
    query_kernel<<<(Q * 32 + 255) / 256, 256>>>(buf1, b2, qe, Wl, bl, out, Q);
}

// round 7
// speedup vs baseline: 2.0981x; 1.3588x over previous
#include <cuda_runtime.h>
#include <cuda_bf16.h>
#include <cstdint>
#include <math.h>

#define N_FEAT 256
#define HIDDEN 256
#define MAX_NODES 50000
#define MAX_EDGES 1000000

// Scratch (__device__ globals per allocation rules)
__device__ float g_buf0[MAX_NODES * HIDDEN]; // h (gemm1 out), then z (gather2 out)
__device__ float g_buf1[MAX_NODES * HIDDEN]; // h1 (gather1 out)
__device__ int   g_cnt[MAX_NODES];
__device__ int   g_rowptr[MAX_NODES + 1];
__device__ int   g_cursor[MAX_NODES];
__device__ int   g_ssrc[MAX_EDGES];
__device__ float g_sw[MAX_EDGES];
__device__ float g_wc[1026];                 // Wc_top[512], Wc_bot[512], c[2]

// ---------------------------------------------------------------------------
// CSR build: zero counts -> histogram -> scan -> fill (edges sorted by dst)
// ---------------------------------------------------------------------------
__global__ void zero_int_kernel(int* __restrict__ p, int n) {
    int i = blockIdx.x * blockDim.x + threadIdx.x;
    for (; i < n; i += gridDim.x * blockDim.x) p[i] = 0;
}

__global__ void hist_kernel(const int* __restrict__ dst, int* __restrict__ cnt, int E) {
    int i = blockIdx.x * blockDim.x + threadIdx.x;
    for (; i < E; i += gridDim.x * blockDim.x)
        atomicAdd(&cnt[dst[i]], 1);
}

// single-block exclusive scan (1024 threads, warp-shuffle based)
__global__ void scan_kernel(const int* __restrict__ cnt, int* __restrict__ rowptr,
                            int* __restrict__ cursor, int n) {
    __shared__ int warpsums[32];
    __shared__ int carry_s;
    int lane = threadIdx.x & 31, wid = threadIdx.x >> 5;
    if (threadIdx.x == 0) carry_s = 0;
    __syncthreads();
    for (int base = 0; base < n; base += blockDim.x) {
        int i = base + threadIdx.x;
        int v = (i < n) ? cnt[i] : 0;
        int x = v;
#pragma unroll
        for (int off = 1; off < 32; off <<= 1) {
            int t = __shfl_up_sync(0xffffffffu, x, off);
            if (lane >= off) x += t;
        }
        if (lane == 31) warpsums[wid] = x;
        __syncthreads();
        if (wid == 0) {
            int s = warpsums[lane];
#pragma unroll
            for (int off = 1; off < 32; off <<= 1) {
                int t = __shfl_up_sync(0xffffffffu, s, off);
                if (lane >= off) s += t;
            }
            warpsums[lane] = s;
        }
        __syncthreads();
        int warp_off = (wid == 0) ? 0 : warpsums[wid - 1];
        int excl = carry_s + warp_off + x - v;
        if (i < n) { rowptr[i] = excl; cursor[i] = excl; }
        __syncthreads();
        if (threadIdx.x == 0) carry_s += warpsums[31];
        __syncthreads();
    }
    if (threadIdx.x == 0) rowptr[n] = carry_s;
}

__global__ void fill_kernel(const int* __restrict__ src, const int* __restrict__ dst,
                            const float* __restrict__ w, int* __restrict__ cursor,
                            int* __restrict__ ssrc, float* __restrict__ sw, int E) {
    int i = blockIdx.x * blockDim.x + threadIdx.x;
    for (; i < E; i += gridDim.x * blockDim.x) {
        int p = atomicAdd(&cursor[dst[i]], 1);
        ssrc[p] = src[i];
        sw[p] = w[i];
    }
}

// ---------------------------------------------------------------------------
// Prep: Wc_top = W2 @ Wl[0:256], Wc_bot = W2 @ Wl[256:512],
//       c = b2 @ (Wl_top + Wl_bot) + bl.  One block, 1024 threads.
// wc layout: [0..511] top as [i][j], [512..1023] bot, [1024..1025] c.
// ---------------------------------------------------------------------------
__global__ void prep_wc_kernel(const float* __restrict__ W2, const float* __restrict__ Wl,
                               const float* __restrict__ b2, const float* __restrict__ bl,
                               float* __restrict__ wc) {
    int tid = threadIdx.x;             // 0..1023
    int half = tid >> 9;               // 0 = top, 1 = bot
    int i = (tid >> 1) & 255;
    int j = tid & 1;
    const float* wlh = Wl + half * 512; // Wl is [512][2]
    float s = 0.f;
#pragma unroll 4
    for (int k = 0; k < 256; k++)
        s += W2[i * 256 + k] * wlh[k * 2 + j];
    wc[half * 512 + i * 2 + j] = s;
    if (tid < 2) {
        float c = bl[tid];
        for (int k = 0; k < 256; k++)
            c += b2[k] * (Wl[k * 2 + tid] + Wl[512 + k * 2 + tid]);
        wc[1024 + tid] = c;
    }
}

// ---------------------------------------------------------------------------
// TF32 tensor-core GEMM: C[M,256] = A[M,256] @ B[256,256]
// ---------------------------------------------------------------------------
#define GBM 128
#define GBN 128
#define GBK 32
#define GPAD 4

__device__ __forceinline__ float tf32_rna(float x) {
    unsigned int u;
    asm("cvt.rna.tf32.f32 %0, %1;" : "=r"(u) : "f"(x));
    return __uint_as_float(u);
}

__device__ __forceinline__ void mma_tf32(float c[4], const unsigned int a[4], const unsigned int b[2]) {
    asm volatile(
        "mma.sync.aligned.m16n8k8.row.col.f32.tf32.tf32.f32 "
        "{%0,%1,%2,%3}, {%4,%5,%6,%7}, {%8,%9}, {%0,%1,%2,%3};"
        : "+f"(c[0]), "+f"(c[1]), "+f"(c[2]), "+f"(c[3])
        : "r"(a[0]), "r"(a[1]), "r"(a[2]), "r"(a[3]), "r"(b[0]), "r"(b[1]));
}

__global__ __launch_bounds__(256, 2)
void gemm_tf32_kernel(const float* __restrict__ A, const float* __restrict__ B,
                      float* __restrict__ C, int M) {
    const int N = 256, K = 256;
    __shared__ float As[GBK][GBM + GPAD];
    __shared__ float Bs[GBK][GBN + GPAD];

    int tid = threadIdx.x;
    int wid = tid >> 5, lane = tid & 31;
    int warp_m = wid & 3;
    int warp_n = wid >> 2;
    int gID = lane >> 2;
    int tig = lane & 3;
    int bx = blockIdx.x, by = blockIdx.y;

    float c[2][8][4];
#pragma unroll
    for (int mi = 0; mi < 2; mi++)
#pragma unroll
        for (int ni = 0; ni < 8; ni++)
#pragma unroll
            for (int r = 0; r < 4; r++) c[mi][ni][r] = 0.f;

    for (int k0 = 0; k0 < K; k0 += GBK) {
#pragma unroll
        for (int t = 0; t < 4; t++) {
            int idx = tid + t * 256;
            int row = idx >> 3;
            int c4 = (idx & 7) * 4;
            int grow = by * GBM + row;
            float4 v = make_float4(0.f, 0.f, 0.f, 0.f);
            if (grow < M)
                v = *(const float4*)(A + (size_t)grow * K + k0 + c4);
            As[c4 + 0][row] = tf32_rna(v.x);
            As[c4 + 1][row] = tf32_rna(v.y);
            As[c4 + 2][row] = tf32_rna(v.z);
            As[c4 + 3][row] = tf32_rna(v.w);
        }
#pragma unroll
        for (int t = 0; t < 4; t++) {
            int idx = tid + t * 256;
            int r = idx >> 5;
            int c4 = (idx & 31) * 4;
            float4 v = *(const float4*)(B + (size_t)(k0 + r) * N + bx * GBN + c4);
            v.x = tf32_rna(v.x); v.y = tf32_rna(v.y);
            v.z = tf32_rna(v.z); v.w = tf32_rna(v.w);
            *(float4*)&Bs[r][c4] = v;
        }
        __syncthreads();

#pragma unroll
        for (int ks = 0; ks < 4; ks++) {
            int kb = ks * 8;
            unsigned int a[2][4];
#pragma unroll
            for (int mi = 0; mi < 2; mi++) {
                int ar = warp_m * 32 + mi * 16 + gID;
                a[mi][0] = __float_as_uint(As[kb + tig][ar]);
                a[mi][1] = __float_as_uint(As[kb + tig][ar + 8]);
                a[mi][2] = __float_as_uint(As[kb + tig + 4][ar]);
                a[mi][3] = __float_as_uint(As[kb + tig + 4][ar + 8]);
            }
            unsigned int b[8][2];
#pragma unroll
            for (int ni = 0; ni < 8; ni++) {
                int bc = warp_n * 64 + ni * 8 + gID;
                b[ni][0] = __float_as_uint(Bs[kb + tig][bc]);
                b[ni][1] = __float_as_uint(Bs[kb + tig + 4][bc]);
            }
#pragma unroll
            for (int mi = 0; mi < 2; mi++)
#pragma unroll
                for (int ni = 0; ni < 8; ni++)
                    mma_tf32(c[mi][ni], a[mi], b[ni]);
        }
        __syncthreads();
    }

#pragma unroll
    for (int mi = 0; mi < 2; mi++) {
        int row0 = by * GBM + warp_m * 32 + mi * 16 + gID;
#pragma unroll
        for (int ni = 0; ni < 8; ni++) {
            int col = bx * GBN + warp_n * 64 + ni * 8 + tig * 2;
            if (row0 < M)
                *(float2*)(C + (size_t)row0 * N + col) = make_float2(c[mi][ni][0], c[mi][ni][1]);
            if (row0 + 8 < M)
                *(float2*)(C + (size_t)(row0 + 8) * N + col) = make_float2(c[mi][ni][2], c[mi][ni][3]);
        }
    }
}

// ---------------------------------------------------------------------------
// Gather aggregation (float4): 4 nodes per 256-thread block, 64 lanes/node.
// out[node] = epilogue( sum_{e in CSR row} w_e * h[src_e] )
// ---------------------------------------------------------------------------
template <int RELU>
__global__ __launch_bounds__(256)
void gather4_kernel(const float4* __restrict__ h4,
                    const int* __restrict__ rowptr,
                    const int* __restrict__ ssrc,
                    const float* __restrict__ sw,
                    const float4* __restrict__ bias4,
                    float4* __restrict__ out4) {
    int grp = threadIdx.x >> 6;        // 0..3
    int t = threadIdx.x & 63;          // float4 column
    int node = blockIdx.x * 4 + grp;
    int beg = rowptr[node], end = rowptr[node + 1];

    float4 acc = make_float4(0.f, 0.f, 0.f, 0.f);
    int i = beg;
    for (; i + 3 < end; i += 4) {
        int s0 = __ldg(&ssrc[i + 0]), s1 = __ldg(&ssrc[i + 1]);
        int s2 = __ldg(&ssrc[i + 2]), s3 = __ldg(&ssrc[i + 3]);
        float w0 = __ldg(&sw[i + 0]), w1 = __ldg(&sw[i + 1]);
        float w2 = __ldg(&sw[i + 2]), w3 = __ldg(&sw[i + 3]);
        float4 v0 = h4[(size_t)s0 * 64 + t];
        float4 v1 = h4[(size_t)s1 * 64 + t];
        float4 v2 = h4[(size_t)s2 * 64 + t];
        float4 v3 = h4[(size_t)s3 * 64 + t];
        acc.x += w0 * v0.x; acc.y += w0 * v0.y; acc.z += w0 * v0.z; acc.w += w0 * v0.w;
        acc.x += w1 * v1.x; acc.y += w1 * v1.y; acc.z += w1 * v1.z; acc.w += w1 * v1.w;
        acc.x += w2 * v2.x; acc.y += w2 * v2.y; acc.z += w2 * v2.z; acc.w += w2 * v2.w;
        acc.x += w3 * v3.x; acc.y += w3 * v3.y; acc.z += w3 * v3.z; acc.w += w3 * v3.w;
    }
    for (; i < end; i++) {
        int s = __ldg(&ssrc[i]);
        float w = __ldg(&sw[i]);
        float4 v = h4[(size_t)s * 64 + t];
        acc.x += w * v.x; acc.y += w * v.y; acc.z += w * v.z; acc.w += w * v.w;
    }

    if (RELU) {
        float4 b = bias4[t];
        acc.x = fmaxf(acc.x + b.x, 0.f);
        acc.y = fmaxf(acc.y + b.y, 0.f);
        acc.z = fmaxf(acc.z + b.z, 0.f);
        acc.w = fmaxf(acc.w + b.w, 0.f);
    }
    out4[(size_t)node * 64 + t] = acc;
}

// ---------------------------------------------------------------------------
// Query: logits = z[q0]@Wc_top + z[q1]@Wc_bot + c; log_softmax. One warp/query.
// ---------------------------------------------------------------------------
__global__ __launch_bounds__(256)
void query_kernel(const float* __restrict__ z,
                  const int* __restrict__ qe,
                  const float* __restrict__ wc,
                  float* __restrict__ out, int Q) {
    __shared__ float sWc[512][2];
    __shared__ float sc[2];
    for (int i = threadIdx.x; i < 512; i += blockDim.x) {
        sWc[i][0] = wc[i * 2 + 0];
        sWc[i][1] = wc[i * 2 + 1];
    }
    if (threadIdx.x < 2) sc[threadIdx.x] = wc[1024 + threadIdx.x];
    __syncthreads();

    int gid = blockIdx.x * blockDim.x + threadIdx.x;
    int q = gid >> 5;
    int lane = gid & 31;
    if (q >= Q) return;

    int r0 = qe[q * 2 + 0];
    int r1 = qe[q * 2 + 1];
    const float* z0 = z + (size_t)r0 * HIDDEN;
    const float* z1 = z + (size_t)r1 * HIDDEN;

    float a0 = 0.f, a1 = 0.f;
#pragma unroll
    for (int t = 0; t < 8; t++) {
        int j = lane + t * 32;
        float v0 = z0[j];
        float v1 = z1[j];
        a0 += v0 * sWc[j][0] + v1 * sWc[256 + j][0];
        a1 += v0 * sWc[j][1] + v1 * sWc[256 + j][1];
    }
#pragma unroll
    for (int off = 16; off > 0; off >>= 1) {
        a0 += __shfl_down_sync(0xffffffffu, a0, off);
        a1 += __shfl_down_sync(0xffffffffu, a1, off);
    }
    if (lane == 0) {
        float l0 = a0 + sc[0];
        float l1 = a1 + sc[1];
        float m = fmaxf(l0, l1);
        float lse = m + logf(expf(l0 - m) + expf(l1 - m));
        out[q * 2 + 0] = l0 - lse;
        out[q * 2 + 1] = l1 - lse;
    }
}

// ---------------------------------------------------------------------------
// Launch
// ---------------------------------------------------------------------------
extern "C" void kernel_launch(void* const* d_in, const int* in_sizes, int n_in,
                              void* d_out, int out_size) {
    const float* x  = (const float*)d_in[0];
    const int*   ei = (const int*)d_in[1];
    const int*   qe = (const int*)d_in[2];
    const float* ew = (const float*)d_in[3];
    const float* W1 = (const float*)d_in[4];
    const float* b1 = (const float*)d_in[5];
    const float* W2 = (const float*)d_in[6];
    const float* b2 = (const float*)d_in[7];
    const float* Wl = (const float*)d_in[8];
    const float* bl = (const float*)d_in[9];
    float* out = (float*)d_out;

    int Nn = in_sizes[0] / N_FEAT;    // 50000
    int E  = in_sizes[1] / 2;
    int Q  = in_sizes[2] / 2;
    const int* src = ei;
    const int* dst = ei + E;

    float* buf0;  cudaGetSymbolAddress((void**)&buf0, g_buf0);
    float* buf1;  cudaGetSymbolAddress((void**)&buf1, g_buf1);
    int* cnt;     cudaGetSymbolAddress((void**)&cnt, g_cnt);
    int* rowptr;  cudaGetSymbolAddress((void**)&rowptr, g_rowptr);
    int* cursor;  cudaGetSymbolAddress((void**)&cursor, g_cursor);
    int* ssrc;    cudaGetSymbolAddress((void**)&ssrc, g_ssrc);
    float* sw;    cudaGetSymbolAddress((void**)&sw, g_sw);
    float* wc;    cudaGetSymbolAddress((void**)&wc, g_wc);

    dim3 gemm_grid(256 / GBN, (Nn + GBM - 1) / GBM);

    // CSR build + Wc precompute
    zero_int_kernel<<<196, 256>>>(cnt, Nn);
    hist_kernel<<<1024, 256>>>(dst, cnt, E);
    prep_wc_kernel<<<1, 1024>>>(W2, Wl, b2, bl, wc);
    scan_kernel<<<1, 1024>>>(cnt, rowptr, cursor, Nn);
    fill_kernel<<<1024, 256>>>(src, dst, ew, cursor, ssrc, sw, E);

    // h = X @ W1 -> buf0 (tf32 tensor cores)
    gemm_tf32_kernel<<<gemm_grid, 256>>>(x, W1, buf0, Nn);
    // h1 = relu(gather(h) + b1) -> buf1
    gather4_kernel<1><<<(Nn + 3) / 4, 256>>>((const float4*)buf0, rowptr, ssrc, sw,
                                             (const float4*)b1, (float4*)buf1);
    // z = gather(h1) -> buf0   (GEMM2 folded into Wc)
    gather4_kernel<0><<<(Nn + 3) / 4, 256>>>((const float4*)buf1, rowptr, ssrc, sw,
                                             (const float4*)b1, (float4*)buf0);
    // logits + log_softmax via Wc
    query_kernel<<<(Q * 32 + 255) / 256, 256>>>(buf0, qe, wc, out, Q);
}

// round 12
// speedup vs baseline: 2.4267x; 1.1566x over previous
#include <cuda_runtime.h>
#include <cuda_fp16.h>
#include <cstdint>
#include <math.h>

#define N_FEAT 256
#define HIDDEN 256
#define MAX_NODES 50000
#define MAX_EDGES 1000000

// Scratch (__device__ globals per allocation rules)
__device__ float g_buf0[MAX_NODES * HIDDEN];     // h (gemm1 out), then z (gather2 out)
__device__ __half g_h1h[MAX_NODES * HIDDEN];     // h1 in fp16 (gather1 out)
__device__ int   g_cnt[MAX_NODES];
__device__ int   g_rowptr[MAX_NODES + 1];
__device__ int   g_cursor[MAX_NODES];
__device__ int   g_ssrc[MAX_EDGES];
__device__ float g_sw[MAX_EDGES];
__device__ float g_wc[1026];                     // Wc_top[512], Wc_bot[512], c[2]
__device__ int   g_bsum[64];
__device__ int   g_boff[64];

// ---------------------------------------------------------------------------
// CSR build: zero -> histogram -> 3-stage multi-block scan -> fill
// ---------------------------------------------------------------------------
__global__ void zero_int_kernel(int* __restrict__ p, int n) {
    int i = blockIdx.x * blockDim.x + threadIdx.x;
    for (; i < n; i += gridDim.x * blockDim.x) p[i] = 0;
}

__global__ void hist_kernel(const int* __restrict__ dst, int* __restrict__ cnt, int E) {
    int i = blockIdx.x * blockDim.x + threadIdx.x;
    for (; i < E; i += gridDim.x * blockDim.x)
        atomicAdd(&cnt[dst[i]], 1);
}

// Stage 1: per-block (1024 elems) exclusive scan; block totals to bsum
__global__ void scan_local_kernel(const int* __restrict__ cnt, int* __restrict__ rowptr,
                                  int* __restrict__ bsum, int n) {
    __shared__ int warpsums[32];
    int tid = threadIdx.x;
    int lane = tid & 31, wid = tid >> 5;
    int i = blockIdx.x * 1024 + tid;
    int v = (i < n) ? cnt[i] : 0;
    int x = v;
#pragma unroll
    for (int off = 1; off < 32; off <<= 1) {
        int t = __shfl_up_sync(0xffffffffu, x, off);
        if (lane >= off) x += t;
    }
    if (lane == 31) warpsums[wid] = x;
    __syncthreads();
    if (wid == 0) {
        int s = warpsums[lane];
#pragma unroll
        for (int off = 1; off < 32; off <<= 1) {
            int t = __shfl_up_sync(0xffffffffu, s, off);
            if (lane >= off) s += t;
        }
        warpsums[lane] = s;
    }
    __syncthreads();
    int warp_off = (wid == 0) ? 0 : warpsums[wid - 1];
    if (i < n) rowptr[i] = warp_off + x - v;
    if (tid == 0) bsum[blockIdx.x] = warpsums[31];
}

// Stage 2: scan the (<=64) block sums; write rowptr[n] = total
__global__ void scan_top_kernel(const int* __restrict__ bsum, int* __restrict__ boff,
                                int* __restrict__ rowptr, int nb, int n) {
    __shared__ int s[64];
    int tid = threadIdx.x;
    int v = (tid < nb) ? bsum[tid] : 0;
    s[tid] = v;
    __syncthreads();
    for (int off = 1; off < 64; off <<= 1) {
        int t = (tid >= off) ? s[tid - off] : 0;
        __syncthreads();
        s[tid] += t;
        __syncthreads();
    }
    if (tid < nb) boff[tid] = s[tid] - v;      // exclusive
    if (tid == nb - 1) rowptr[n] = s[tid];     // grand total
}

// Stage 3: add block offsets; init cursor
__global__ void scan_addoff_kernel(int* __restrict__ rowptr, int* __restrict__ cursor,
                                   const int* __restrict__ boff, int n) {
    int i = blockIdx.x * blockDim.x + threadIdx.x;
    for (; i < n; i += gridDim.x * blockDim.x) {
        int r = rowptr[i] + boff[i >> 10];
        rowptr[i] = r;
        cursor[i] = r;
    }
}

__global__ void fill_kernel(const int* __restrict__ src, const int* __restrict__ dst,
                            const float* __restrict__ w, int* __restrict__ cursor,
                            int* __restrict__ ssrc, float* __restrict__ sw, int E) {
    int i = blockIdx.x * blockDim.x + threadIdx.x;
    for (; i < E; i += gridDim.x * blockDim.x) {
        int p = atomicAdd(&cursor[dst[i]], 1);
        ssrc[p] = src[i];
        sw[p] = w[i];
    }
}

// ---------------------------------------------------------------------------
// Prep: Wc_top = W2 @ Wl[0:256], Wc_bot = W2 @ Wl[256:512],
//       c = b2 @ (Wl_top + Wl_bot) + bl.  One block, 1024 threads.
// ---------------------------------------------------------------------------
__global__ void prep_wc_kernel(const float* __restrict__ W2, const float* __restrict__ Wl,
                               const float* __restrict__ b2, const float* __restrict__ bl,
                               float* __restrict__ wc) {
    int tid = threadIdx.x;
    int half = tid >> 9;
    int i = (tid >> 1) & 255;
    int j = tid & 1;
    const float* wlh = Wl + half * 512;
    float s = 0.f;
#pragma unroll 4
    for (int k = 0; k < 256; k++)
        s += W2[i * 256 + k] * wlh[k * 2 + j];
    wc[half * 512 + i * 2 + j] = s;
    if (tid < 2) {
        float c = bl[tid];
        for (int k = 0; k < 256; k++)
            c += b2[k] * (Wl[k * 2 + tid] + Wl[512 + k * 2 + tid]);
        wc[1024 + tid] = c;
    }
}

// ---------------------------------------------------------------------------
// TF32 tensor-core GEMM: C[M,256] = A[M,256] @ B[256,256]
// ---------------------------------------------------------------------------
#define GBM 128
#define GBN 128
#define GBK 32
#define GPAD 4

__device__ __forceinline__ float tf32_rna(float x) {
    unsigned int u;
    asm("cvt.rna.tf32.f32 %0, %1;" : "=r"(u) : "f"(x));
    return __uint_as_float(u);
}

__device__ __forceinline__ void mma_tf32(float c[4], const unsigned int a[4], const unsigned int b[2]) {
    asm volatile(
        "mma.sync.aligned.m16n8k8.row.col.f32.tf32.tf32.f32 "
        "{%0,%1,%2,%3}, {%4,%5,%6,%7}, {%8,%9}, {%0,%1,%2,%3};"
        : "+f"(c[0]), "+f"(c[1]), "+f"(c[2]), "+f"(c[3])
        : "r"(a[0]), "r"(a[1]), "r"(a[2]), "r"(a[3]), "r"(b[0]), "r"(b[1]));
}

__global__ __launch_bounds__(256, 2)
void gemm_tf32_kernel(const float* __restrict__ A, const float* __restrict__ B,
                      float* __restrict__ C, int M) {
    const int N = 256, K = 256;
    __shared__ float As[GBK][GBM + GPAD];
    __shared__ float Bs[GBK][GBN + GPAD];

    int tid = threadIdx.x;
    int wid = tid >> 5, lane = tid & 31;
    int warp_m = wid & 3;
    int warp_n = wid >> 2;
    int gID = lane >> 2;
    int tig = lane & 3;
    int bx = blockIdx.x, by = blockIdx.y;

    float c[2][8][4];
#pragma unroll
    for (int mi = 0; mi < 2; mi++)
#pragma unroll
        for (int ni = 0; ni < 8; ni++)
#pragma unroll
            for (int r = 0; r < 4; r++) c[mi][ni][r] = 0.f;

    for (int k0 = 0; k0 < K; k0 += GBK) {
#pragma unroll
        for (int t = 0; t < 4; t++) {
            int idx = tid + t * 256;
            int row = idx >> 3;
            int c4 = (idx & 7) * 4;
            int grow = by * GBM + row;
            float4 v = make_float4(0.f, 0.f, 0.f, 0.f);
            if (grow < M)
                v = *(const float4*)(A + (size_t)grow * K + k0 + c4);
            As[c4 + 0][row] = tf32_rna(v.x);
            As[c4 + 1][row] = tf32_rna(v.y);
            As[c4 + 2][row] = tf32_rna(v.z);
            As[c4 + 3][row] = tf32_rna(v.w);
        }
#pragma unroll
        for (int t = 0; t < 4; t++) {
            int idx = tid + t * 256;
            int r = idx >> 5;
            int c4 = (idx & 31) * 4;
            float4 v = *(const float4*)(B + (size_t)(k0 + r) * N + bx * GBN + c4);
            v.x = tf32_rna(v.x); v.y = tf32_rna(v.y);
            v.z = tf32_rna(v.z); v.w = tf32_rna(v.w);
            *(float4*)&Bs[r][c4] = v;
        }
        __syncthreads();

#pragma unroll
        for (int ks = 0; ks < 4; ks++) {
            int kb = ks * 8;
            unsigned int a[2][4];
#pragma unroll
            for (int mi = 0; mi < 2; mi++) {
                int ar = warp_m * 32 + mi * 16 + gID;
                a[mi][0] = __float_as_uint(As[kb + tig][ar]);
                a[mi][1] = __float_as_uint(As[kb + tig][ar + 8]);
                a[mi][2] = __float_as_uint(As[kb + tig + 4][ar]);
                a[mi][3] = __float_as_uint(As[kb + tig + 4][ar + 8]);
            }
            unsigned int b[8][2];
#pragma unroll
            for (int ni = 0; ni < 8; ni++) {
                int bc = warp_n * 64 + ni * 8 + gID;
                b[ni][0] = __float_as_uint(Bs[kb + tig][bc]);
                b[ni][1] = __float_as_uint(Bs[kb + tig + 4][bc]);
            }
#pragma unroll
            for (int mi = 0; mi < 2; mi++)
#pragma unroll
                for (int ni = 0; ni < 8; ni++)
                    mma_tf32(c[mi][ni], a[mi], b[ni]);
        }
        __syncthreads();
    }

#pragma unroll
    for (int mi = 0; mi < 2; mi++) {
        int row0 = by * GBM + warp_m * 32 + mi * 16 + gID;
#pragma unroll
        for (int ni = 0; ni < 8; ni++) {
            int col = bx * GBN + warp_n * 64 + ni * 8 + tig * 2;
            if (row0 < M)
                *(float2*)(C + (size_t)row0 * N + col) = make_float2(c[mi][ni][0], c[mi][ni][1]);
            if (row0 + 8 < M)
                *(float2*)(C + (size_t)(row0 + 8) * N + col) = make_float2(c[mi][ni][2], c[mi][ni][3]);
        }
    }
}

// ---------------------------------------------------------------------------
// Gather1: h (fp32) -> h1 = relu(agg + b1) stored as fp16.
// 4 nodes per 256-thread block, 64 lanes/node, float4 loads.
// ---------------------------------------------------------------------------
__global__ __launch_bounds__(256)
void gather1_kernel(const float4* __restrict__ h4,
                    const int* __restrict__ rowptr,
                    const int* __restrict__ ssrc,
                    const float* __restrict__ sw,
                    const float4* __restrict__ bias4,
                    __half2* __restrict__ out2) {
    int grp = threadIdx.x >> 6;
    int t = threadIdx.x & 63;
    int node = blockIdx.x * 4 + grp;
    int beg = rowptr[node], end = rowptr[node + 1];

    float4 acc = make_float4(0.f, 0.f, 0.f, 0.f);
    int i = beg;
    for (; i + 3 < end; i += 4) {
        int s0 = __ldg(&ssrc[i + 0]), s1 = __ldg(&ssrc[i + 1]);
        int s2 = __ldg(&ssrc[i + 2]), s3 = __ldg(&ssrc[i + 3]);
        float w0 = __ldg(&sw[i + 0]), w1 = __ldg(&sw[i + 1]);
        float w2 = __ldg(&sw[i + 2]), w3 = __ldg(&sw[i + 3]);
        float4 v0 = h4[(size_t)s0 * 64 + t];
        float4 v1 = h4[(size_t)s1 * 64 + t];
        float4 v2 = h4[(size_t)s2 * 64 + t];
        float4 v3 = h4[(size_t)s3 * 64 + t];
        acc.x += w0 * v0.x; acc.y += w0 * v0.y; acc.z += w0 * v0.z; acc.w += w0 * v0.w;
        acc.x += w1 * v1.x; acc.y += w1 * v1.y; acc.z += w1 * v1.z; acc.w += w1 * v1.w;
        acc.x += w2 * v2.x; acc.y += w2 * v2.y; acc.z += w2 * v2.z; acc.w += w2 * v2.w;
        acc.x += w3 * v3.x; acc.y += w3 * v3.y; acc.z += w3 * v3.z; acc.w += w3 * v3.w;
    }
    for (; i < end; i++) {
        int s = __ldg(&ssrc[i]);
        float w = __ldg(&sw[i]);
        float4 v = h4[(size_t)s * 64 + t];
        acc.x += w * v.x; acc.y += w * v.y; acc.z += w * v.z; acc.w += w * v.w;
    }

    float4 b = bias4[t];
    acc.x = fmaxf(acc.x + b.x, 0.f);
    acc.y = fmaxf(acc.y + b.y, 0.f);
    acc.z = fmaxf(acc.z + b.z, 0.f);
    acc.w = fmaxf(acc.w + b.w, 0.f);

    // 4 floats -> 2x half2, 8-byte store
    out2[(size_t)node * 128 + t * 2 + 0] = __floats2half2_rn(acc.x, acc.y);
    out2[(size_t)node * 128 + t * 2 + 1] = __floats2half2_rn(acc.z, acc.w);
}

// ---------------------------------------------------------------------------
// Gather2: h1 (fp16) -> z (fp32). 8 nodes per 256-thread block, 32 lanes/node,
// uint4 loads (8 halfs each), fp32 accumulate.
// ---------------------------------------------------------------------------
__global__ __launch_bounds__(256)
void gather2_kernel(const uint4* __restrict__ h1,   // 32 uint4 per row
                    const int* __restrict__ rowptr,
                    const int* __restrict__ ssrc,
                    const float* __restrict__ sw,
                    float4* __restrict__ out4) {
    int grp = threadIdx.x >> 5;        // 0..7
    int lane = threadIdx.x & 31;       // uint4 column (8 features)
    int node = blockIdx.x * 8 + grp;
    int beg = rowptr[node], end = rowptr[node + 1];

    float acc[8];
#pragma unroll
    for (int k = 0; k < 8; k++) acc[k] = 0.f;

#define G2_ACC(vv, ww) { \
        const __half2* p = (const __half2*)&(vv); \
        _Pragma("unroll") \
        for (int k = 0; k < 4; k++) { \
            float2 f = __half22float2(p[k]); \
            acc[2 * k + 0] += (ww) * f.x; \
            acc[2 * k + 1] += (ww) * f.y; \
        } }

    int i = beg;
    for (; i + 3 < end; i += 4) {
        int s0 = __ldg(&ssrc[i + 0]), s1 = __ldg(&ssrc[i + 1]);
        int s2 = __ldg(&ssrc[i + 2]), s3 = __ldg(&ssrc[i + 3]);
        float w0 = __ldg(&sw[i + 0]), w1 = __ldg(&sw[i + 1]);
        float w2 = __ldg(&sw[i + 2]), w3 = __ldg(&sw[i + 3]);
        uint4 v0 = h1[(size_t)s0 * 32 + lane];
        uint4 v1 = h1[(size_t)s1 * 32 + lane];
        uint4 v2 = h1[(size_t)s2 * 32 + lane];
        uint4 v3 = h1[(size_t)s3 * 32 + lane];
        G2_ACC(v0, w0);
        G2_ACC(v1, w1);
        G2_ACC(v2, w2);
        G2_ACC(v3, w3);
    }
    for (; i < end; i++) {
        int s = __ldg(&ssrc[i]);
        float w = __ldg(&sw[i]);
        uint4 v = h1[(size_t)s * 32 + lane];
        G2_ACC(v, w);
    }
#undef G2_ACC

    out4[(size_t)node * 64 + lane * 2 + 0] = make_float4(acc[0], acc[1], acc[2], acc[3]);
    out4[(size_t)node * 64 + lane * 2 + 1] = make_float4(acc[4], acc[5], acc[6], acc[7]);
}

// ---------------------------------------------------------------------------
// Query: logits = z[q0]@Wc_top + z[q1]@Wc_bot + c; log_softmax. One warp/query.
// ---------------------------------------------------------------------------
__global__ __launch_bounds__(256)
void query_kernel(const float* __restrict__ z,
                  const int* __restrict__ qe,
                  const float* __restrict__ wc,
                  float* __restrict__ out, int Q) {
    __shared__ float sWc[512][2];
    __shared__ float sc[2];
    for (int i = threadIdx.x; i < 512; i += blockDim.x) {
        sWc[i][0] = wc[i * 2 + 0];
        sWc[i][1] = wc[i * 2 + 1];
    }
    if (threadIdx.x < 2) sc[threadIdx.x] = wc[1024 + threadIdx.x];
    __syncthreads();

    int gid = blockIdx.x * blockDim.x + threadIdx.x;
    int q = gid >> 5;
    int lane = gid & 31;
    if (q >= Q) return;

    int r0 = qe[q * 2 + 0];
    int r1 = qe[q * 2 + 1];
    const float* z0 = z + (size_t)r0 * HIDDEN;
    const float* z1 = z + (size_t)r1 * HIDDEN;

    float a0 = 0.f, a1 = 0.f;
#pragma unroll
    for (int t = 0; t < 8; t++) {
        int j = lane + t * 32;
        float v0 = z0[j];
        float v1 = z1[j];
        a0 += v0 * sWc[j][0] + v1 * sWc[256 + j][0];
        a1 += v0 * sWc[j][1] + v1 * sWc[256 + j][1];
    }
#pragma unroll
    for (int off = 16; off > 0; off >>= 1) {
        a0 += __shfl_down_sync(0xffffffffu, a0, off);
        a1 += __shfl_down_sync(0xffffffffu, a1, off);
    }
    if (lane == 0) {
        float l0 = a0 + sc[0];
        float l1 = a1 + sc[1];
        float m = fmaxf(l0, l1);
        float lse = m + logf(expf(l0 - m) + expf(l1 - m));
        out[q * 2 + 0] = l0 - lse;
        out[q * 2 + 1] = l1 - lse;
    }
}

// ---------------------------------------------------------------------------
// Launch
// ---------------------------------------------------------------------------
extern "C" void kernel_launch(void* const* d_in, const int* in_sizes, int n_in,
                              void* d_out, int out_size) {
    const float* x  = (const float*)d_in[0];
    const int*   ei = (const int*)d_in[1];
    const int*   qe = (const int*)d_in[2];
    const float* ew = (const float*)d_in[3];
    const float* W1 = (const float*)d_in[4];
    const float* b1 = (const float*)d_in[5];
    const float* W2 = (const float*)d_in[6];
    const float* b2 = (const float*)d_in[7];
    const float* Wl = (const float*)d_in[8];
    const float* bl = (const float*)d_in[9];
    float* out = (float*)d_out;

    int Nn = in_sizes[0] / N_FEAT;    // 50000
    int E  = in_sizes[1] / 2;
    int Q  = in_sizes[2] / 2;
    const int* src = ei;
    const int* dst = ei + E;

    float* buf0;  cudaGetSymbolAddress((void**)&buf0, g_buf0);
    __half* h1h;  cudaGetSymbolAddress((void**)&h1h, g_h1h);
    int* cnt;     cudaGetSymbolAddress((void**)&cnt, g_cnt);
    int* rowptr;  cudaGetSymbolAddress((void**)&rowptr, g_rowptr);
    int* cursor;  cudaGetSymbolAddress((void**)&cursor, g_cursor);
    int* ssrc;    cudaGetSymbolAddress((void**)&ssrc, g_ssrc);
    float* sw;    cudaGetSymbolAddress((void**)&sw, g_sw);
    float* wc;    cudaGetSymbolAddress((void**)&wc, g_wc);
    int* bsum;    cudaGetSymbolAddress((void**)&bsum, g_bsum);
    int* boff;    cudaGetSymbolAddress((void**)&boff, g_boff);

    dim3 gemm_grid(256 / GBN, (Nn + GBM - 1) / GBM);
    int nb = (Nn + 1023) / 1024;      // 49

    // CSR build + Wc precompute
    zero_int_kernel<<<196, 256>>>(cnt, Nn);
    hist_kernel<<<1024, 256>>>(dst, cnt, E);
    prep_wc_kernel<<<1, 1024>>>(W2, Wl, b2, bl, wc);
    scan_local_kernel<<<nb, 1024>>>(cnt, rowptr, bsum, Nn);
    scan_top_kernel<<<1, 64>>>(bsum, boff, rowptr, nb, Nn);
    scan_addoff_kernel<<<196, 256>>>(rowptr, cursor, boff, Nn);
    fill_kernel<<<1024, 256>>>(src, dst, ew, cursor, ssrc, sw, E);

    // h = X @ W1 -> buf0 (tf32 tensor cores)
    gemm_tf32_kernel<<<gemm_grid, 256>>>(x, W1, buf0, Nn);
    // h1 = relu(gather(h) + b1) -> fp16
    gather1_kernel<<<(Nn + 3) / 4, 256>>>((const float4*)buf0, rowptr, ssrc, sw,
                                          (const float4*)b1, (__half2*)h1h);
    // z = gather(h1) -> buf0 (fp32; GEMM2 folded into Wc)
    gather2_kernel<<<(Nn + 7) / 8, 256>>>((const uint4*)h1h, rowptr, ssrc, sw,
                                          (float4*)buf0);
    // logits + log_softmax via Wc
    query_kernel<<<(Q * 32 + 255) / 256, 256>>>(buf0, qe, wc, out, Q);
}